// round 1
// baseline (speedup 1.0000x reference)
#include <cuda_runtime.h>

#define MAXN   500000
#define IN     128
#define H1     32
#define H2     32
#define NOS    4
#define TM     128                 // atoms per MLP tile/block
#define MAXNB  3912                // >= ceil(MAXN/TM) + NOS slack
#define PADN   (MAXNB * TM)
#define SMEM_BYTES 105360

// ---------------- device scratch (no allocations allowed) ----------------
__device__ int   g_is64;
__device__ int   g_counts[NOS];
__device__ int   g_base[NOS];
__device__ int   g_cursor[NOS];
__device__ int   g_order[PADN];
__device__ float g_partial[MAXNB];

__device__ __forceinline__ int ld_species(const void* sp, int i) {
    if (g_is64) return (int)((const long long*)sp)[i];
    return ((const int*)sp)[i];
}

// ---------------- init: zero counters + detect int32 vs int64 species ----
__global__ void k_init(const unsigned long long* sp, int n) {
    __shared__ int bad;
    if (threadIdx.x == 0) bad = 0;
    if (threadIdx.x < NOS) g_counts[threadIdx.x] = 0;
    __syncthreads();
    int lim = (n / 2 < 2048) ? (n / 2) : 2048;   // safe to read as u64 either way
    for (int i = threadIdx.x; i < lim; i += 256) {
        if (sp[i] >= 4ull) bad = 1;              // int32 data: high word holds next value
    }
    __syncthreads();
    if (threadIdx.x == 0) g_is64 = bad ? 0 : 1;
}

// ---------------- histogram ----------------
__global__ void k_count(const void* sp, int n) {
    __shared__ int h[NOS];
    if (threadIdx.x < NOS) h[threadIdx.x] = 0;
    __syncthreads();
    int i = blockIdx.x * blockDim.x + threadIdx.x;
    if (i < n) atomicAdd(&h[ld_species(sp, i)], 1);
    __syncthreads();
    if (threadIdx.x < NOS && h[threadIdx.x] > 0)
        atomicAdd(&g_counts[threadIdx.x], h[threadIdx.x]);
}

// ---------------- tile-aligned segment bases ----------------
__global__ void k_offsets() {
    int base = 0;
#pragma unroll
    for (int s = 0; s < NOS; s++) {
        g_base[s]   = base;
        g_cursor[s] = base;
        base += ((g_counts[s] + TM - 1) / TM) * TM;
    }
}

// ---------------- fill order with sentinel ----------------
__global__ void k_fill(int padn) {
    int i = blockIdx.x * blockDim.x + threadIdx.x;
    if (i < padn) g_order[i] = -1;
}

// ---------------- scatter atom indices into species segments ------------
__global__ void k_scatter(const void* sp, int n) {
    __shared__ int h[NOS];
    __shared__ int basebuf[NOS];
    if (threadIdx.x < NOS) h[threadIdx.x] = 0;
    __syncthreads();
    int i = blockIdx.x * blockDim.x + threadIdx.x;
    int s = 0, r = 0;
    bool valid = (i < n);
    if (valid) {
        s = ld_species(sp, i);
        r = atomicAdd(&h[s], 1);
    }
    __syncthreads();
    if (threadIdx.x < NOS && h[threadIdx.x] > 0)
        basebuf[threadIdx.x] = atomicAdd(&g_cursor[threadIdx.x], h[threadIdx.x]);
    __syncthreads();
    if (valid) g_order[basebuf[s] + r] = i;
}

// ---------------- fused MLP over one 128-atom, single-species tile ------
__global__ void __launch_bounds__(256, 2) k_mlp(
    const float* __restrict__ desc,
    const float* __restrict__ W0, const float* __restrict__ b0,
    const float* __restrict__ W1, const float* __restrict__ b1,
    const float* __restrict__ W2, const float* __restrict__ b2)
{
    extern __shared__ float sm[];
    float* sW0  = sm;                      // 4096  [k*32+j]
    float* sW1  = sW0 + IN * H1;           // 1024  [k*32+j]
    float* sb0  = sW1 + H1 * H2;           // 32
    float* sb1  = sb0 + 32;                // 32
    float* sW2  = sb1 + 32;                // 32
    float* sb2  = sW2 + 32;                // 4 (pad)
    int*   sidx = (int*)(sb2 + 4);         // 128
    float* sred = (float*)(sidx + 128);    // 128
    float* sdesc = sred + 128;             // 128 * 130 (stride 130: conflict-free)
    float* sh1   = sdesc + 128 * 130;      // 128 * 33
    float* sh2   = sdesc;                  // alias (desc dead after layer0)

    const int t     = threadIdx.x;
    const int tile0 = blockIdx.x * TM;

    // species of this (single-species, tile-aligned) segment
    int sp = 0;
#pragma unroll
    for (int s = 1; s < NOS; s++) if (tile0 >= g_base[s]) sp = s;

    for (int i = t; i < IN * H1; i += 256) sW0[i] = W0[sp * IN * H1 + i];
    for (int i = t; i < H1 * H2; i += 256) sW1[i] = W1[sp * H1 * H2 + i];
    if (t < H1) sb0[t] = b0[sp * H1 + t];
    if (t < H2) { sb1[t] = b1[sp * H2 + t]; sW2[t] = W2[sp * H2 + t]; }
    if (t == 0) sb2[0] = b2[sp];
    if (t < TM) sidx[t] = g_order[tile0 + t];
    __syncthreads();

    // stage desc tile: warp per row, float4 coalesced global, padded shared
    {
        const int w = t >> 5, l = t & 31;
#pragma unroll
        for (int rr = 0; rr < TM / 8; rr++) {
            int row = rr * 8 + w;
            int idx = sidx[row];
            float4 v = make_float4(0.f, 0.f, 0.f, 0.f);
            if (idx >= 0)
                v = *(const float4*)(desc + (size_t)idx * IN + l * 4);
            float* dst = &sdesc[row * 130 + l * 4];
            dst[0] = v.x; dst[1] = v.y; dst[2] = v.z; dst[3] = v.w;
        }
    }
    __syncthreads();

    const int jg = t & 7;    // output-col group: cols jg*4 .. +3
    const int ag = t >> 3;   // atom group: atoms ag*4 .. +3
    const float* dp = &sdesc[ag * 4 * 130];

    // -------- layer 0: [128 x 128] @ [128 x 32], 4x4 register tile ------
    float acc[4][4];
#pragma unroll
    for (int r = 0; r < 4; r++)
#pragma unroll
        for (int c = 0; c < 4; c++) acc[r][c] = sb0[jg * 4 + c];

#pragma unroll 8
    for (int k = 0; k < IN; k++) {
        float4 wv = *(const float4*)&sW0[k * H1 + jg * 4];
        float d0 = dp[0 * 130 + k];
        float d1 = dp[1 * 130 + k];
        float d2 = dp[2 * 130 + k];
        float d3 = dp[3 * 130 + k];
        acc[0][0] += d0 * wv.x; acc[0][1] += d0 * wv.y; acc[0][2] += d0 * wv.z; acc[0][3] += d0 * wv.w;
        acc[1][0] += d1 * wv.x; acc[1][1] += d1 * wv.y; acc[1][2] += d1 * wv.z; acc[1][3] += d1 * wv.w;
        acc[2][0] += d2 * wv.x; acc[2][1] += d2 * wv.y; acc[2][2] += d2 * wv.z; acc[2][3] += d2 * wv.w;
        acc[3][0] += d3 * wv.x; acc[3][1] += d3 * wv.y; acc[3][2] += d3 * wv.z; acc[3][3] += d3 * wv.w;
    }
#pragma unroll
    for (int r = 0; r < 4; r++)
#pragma unroll
        for (int c = 0; c < 4; c++)
            sh1[(ag * 4 + r) * 33 + jg * 4 + c] = tanhf(acc[r][c]);
    __syncthreads();

    // -------- layer 1: [128 x 32] @ [32 x 32] ---------------------------
#pragma unroll
    for (int r = 0; r < 4; r++)
#pragma unroll
        for (int c = 0; c < 4; c++) acc[r][c] = sb1[jg * 4 + c];

    const float* hp = &sh1[ag * 4 * 33];
#pragma unroll
    for (int k = 0; k < H1; k++) {
        float4 wv = *(const float4*)&sW1[k * H2 + jg * 4];
        float d0 = hp[0 * 33 + k];
        float d1 = hp[1 * 33 + k];
        float d2 = hp[2 * 33 + k];
        float d3 = hp[3 * 33 + k];
        acc[0][0] += d0 * wv.x; acc[0][1] += d0 * wv.y; acc[0][2] += d0 * wv.z; acc[0][3] += d0 * wv.w;
        acc[1][0] += d1 * wv.x; acc[1][1] += d1 * wv.y; acc[1][2] += d1 * wv.z; acc[1][3] += d1 * wv.w;
        acc[2][0] += d2 * wv.x; acc[2][1] += d2 * wv.y; acc[2][2] += d2 * wv.z; acc[2][3] += d2 * wv.w;
        acc[3][0] += d3 * wv.x; acc[3][1] += d3 * wv.y; acc[3][2] += d3 * wv.z; acc[3][3] += d3 * wv.w;
    }
#pragma unroll
    for (int r = 0; r < 4; r++)
#pragma unroll
        for (int c = 0; c < 4; c++)
            sh2[(ag * 4 + r) * 33 + jg * 4 + c] = tanhf(acc[r][c]);
    __syncthreads();

    // -------- layer 2 + per-atom energy ---------------------------------
    if (t < TM) {
        float e = 0.f;
        if (sidx[t] >= 0) {
            e = sb2[0];
#pragma unroll
            for (int j = 0; j < H2; j++) e += sh2[t * 33 + j] * sW2[j];
        }
        sred[t] = e;
    }
    __syncthreads();

    // -------- deterministic block reduction ------------------------------
    if (t < 64) sred[t] += sred[t + 64];
    __syncthreads();
    if (t < 32) {
        float v = sred[t] + sred[t + 32];
#pragma unroll
        for (int o = 16; o > 0; o >>= 1) v += __shfl_down_sync(0xffffffffu, v, o);
        if (t == 0) g_partial[blockIdx.x] = v;
    }
}

// ---------------- deterministic final reduction ----------------
__global__ void k_reduce(float* out, int nb) {
    __shared__ float s[1024];
    const int t = threadIdx.x;
    float v = 0.f;
    for (int i = t; i < nb; i += 1024) v += g_partial[i];
    s[t] = v;
    __syncthreads();
#pragma unroll
    for (int o = 512; o > 32; o >>= 1) {
        if (t < o) s[t] += s[t + o];
        __syncthreads();
    }
    if (t < 32) {
        float x = s[t] + s[t + 32];
#pragma unroll
        for (int o = 16; o > 0; o >>= 1) x += __shfl_down_sync(0xffffffffu, x, o);
        if (t == 0) out[0] = x;
    }
}

// ---------------- launcher ----------------
extern "C" void kernel_launch(void* const* d_in, const int* in_sizes, int n_in,
                              void* d_out, int out_size)
{
    const float* desc    = (const float*)d_in[0];
    const void*  species = d_in[1];
    const float* W0 = (const float*)d_in[2];
    const float* b0 = (const float*)d_in[3];
    const float* W1 = (const float*)d_in[4];
    const float* b1 = (const float*)d_in[5];
    const float* W2 = (const float*)d_in[6];
    const float* b2 = (const float*)d_in[7];

    int n = in_sizes[1];
    if (n > MAXN) n = MAXN;

    int nb_atoms = (n + 255) / 256;
    int nb_mlp   = (n + TM - 1) / TM + NOS;   // slack for per-species tile padding
    if (nb_mlp > MAXNB) nb_mlp = MAXNB;
    int padn = nb_mlp * TM;

    cudaFuncSetAttribute(k_mlp, cudaFuncAttributeMaxDynamicSharedMemorySize, SMEM_BYTES);

    k_init<<<1, 256>>>((const unsigned long long*)species, n);
    k_count<<<nb_atoms, 256>>>(species, n);
    k_offsets<<<1, 1>>>();
    k_fill<<<(padn + 255) / 256, 256>>>(padn);
    k_scatter<<<nb_atoms, 256>>>(species, n);
    k_mlp<<<nb_mlp, 256, SMEM_BYTES>>>(desc, W0, b0, W1, b1, W2, b2);
    k_reduce<<<1, 1024>>>((float*)d_out, nb_mlp);
}

// round 2
// speedup vs baseline: 1.1067x; 1.1067x over previous
#include <cuda_runtime.h>

#define MAXN   500000
#define IN     128
#define H1     32
#define H2     32
#define NOS    4
#define TM     128                 // atoms per MLP tile/block
#define MAXNB  3912                // >= ceil(MAXN/TM) + NOS slack
#define PADN   (MAXNB * TM)
#define SMEM_FLOATS 25956
#define SMEM_BYTES  (SMEM_FLOATS * 4)

typedef unsigned long long ull;

// packed dual-FMA: acc.{lo,hi} += x.{lo,hi} * y.{lo,hi}
#define FFMA2(acc, x, y) asm("fma.rn.f32x2 %0, %1, %2, %0;" : "+l"(acc) : "l"(x), "l"(y))

__device__ __forceinline__ float pairsum(ull v) {
    float lo, hi;
    asm("mov.b64 {%0,%1}, %2;" : "=f"(lo), "=f"(hi) : "l"(v));
    return lo + hi;
}

// tanh(x) = 1 - 2/(exp(2x)+1); exact at +/-inf, ~1e-6 rel err
__device__ __forceinline__ float fast_tanh(float x) {
    float e, r;
    asm("ex2.approx.f32 %0, %1;" : "=f"(e) : "f"(x * 2.885390081777927f));
    asm("rcp.approx.f32 %0, %1;" : "=f"(r) : "f"(e + 1.0f));
    return fmaf(-2.0f, r, 1.0f);
}

// ---------------- device scratch ----------------
__device__ int   g_is64;
__device__ int   g_counts[NOS];
__device__ int   g_base[NOS];
__device__ int   g_cursor[NOS];
__device__ int   g_total;
__device__ int   g_order[PADN];
__device__ float g_partial[MAXNB];

__device__ __forceinline__ int ld_species(const void* sp, int i) {
    if (g_is64) return (int)((const long long*)sp)[i];
    return ((const int*)sp)[i];
}

// ---------------- init: zero counters + detect int32 vs int64 ----------
__global__ void k_init(const unsigned long long* sp, int n) {
    __shared__ int bad;
    if (threadIdx.x == 0) bad = 0;
    if (threadIdx.x < NOS) g_counts[threadIdx.x] = 0;
    __syncthreads();
    int lim = (n / 2 < 2048) ? (n / 2) : 2048;
    for (int i = threadIdx.x; i < lim; i += 256)
        if (sp[i] >= 4ull) bad = 1;
    __syncthreads();
    if (threadIdx.x == 0) g_is64 = bad ? 0 : 1;
}

// ---------------- histogram ----------------
__global__ void k_count(const void* sp, int n) {
    __shared__ int h[NOS];
    if (threadIdx.x < NOS) h[threadIdx.x] = 0;
    __syncthreads();
    int i = blockIdx.x * blockDim.x + threadIdx.x;
    if (i < n) atomicAdd(&h[ld_species(sp, i)], 1);
    __syncthreads();
    if (threadIdx.x < NOS && h[threadIdx.x] > 0)
        atomicAdd(&g_counts[threadIdx.x], h[threadIdx.x]);
}

// ---------------- tile-aligned segment bases ----------------
__global__ void k_offsets() {
    int base = 0;
#pragma unroll
    for (int s = 0; s < NOS; s++) {
        g_base[s]   = base;
        g_cursor[s] = base;
        base += ((g_counts[s] + TM - 1) / TM) * TM;
    }
    g_total = base;
}

// ---------------- write -1 only into per-species pad gaps --------------
__global__ void k_pad() {
    int t = threadIdx.x;
    int s = t / TM, j = t % TM;
    int cnt  = g_counts[s];
    int tile = ((cnt + TM - 1) / TM) * TM;
    int pos  = cnt + j;
    if (pos < tile) g_order[g_base[s] + pos] = -1;
}

// ---------------- scatter atom indices into species segments -----------
__global__ void k_scatter(const void* sp, int n) {
    __shared__ int h[NOS];
    __shared__ int basebuf[NOS];
    if (threadIdx.x < NOS) h[threadIdx.x] = 0;
    __syncthreads();
    int i = blockIdx.x * blockDim.x + threadIdx.x;
    int s = 0, r = 0;
    bool valid = (i < n);
    if (valid) {
        s = ld_species(sp, i);
        r = atomicAdd(&h[s], 1);
    }
    __syncthreads();
    if (threadIdx.x < NOS && h[threadIdx.x] > 0)
        basebuf[threadIdx.x] = atomicAdd(&g_cursor[threadIdx.x], h[threadIdx.x]);
    __syncthreads();
    if (valid) g_order[basebuf[s] + r] = i;
}

// ---------------- fused MLP, f32x2-packed, swizzled smem ---------------
__global__ void __launch_bounds__(256, 2) k_mlp(
    const float* __restrict__ desc,
    const float* __restrict__ W0, const float* __restrict__ b0,
    const float* __restrict__ W1, const float* __restrict__ b1,
    const float* __restrict__ W2, const float* __restrict__ b2)
{
    extern __shared__ float sm[];
    float* sW0T  = sm;             // [c=32][k=128] swizzled, 4096
    float* sW1T  = sm + 4096;      // [c=32][k=32]  swizzled, 1024
    float* sb0   = sm + 5120;      // 32
    float* sb1   = sm + 5152;      // 32
    float* sW2   = sm + 5184;      // 32
    float* sb2   = sm + 5216;      // 4
    float* sdesc = sm + 5220;      // [row=128][k=128] swizzled, 16384
    float* sh1   = sm + 21604;     // [row=128][k=32]  swizzled, 4096
    float* sh2   = sdesc;          // alias: desc dead after layer0
    int*   sidx  = (int*)(sm + 25700);  // 128
    float* sred  = sm + 25828;          // 128

    const int t     = threadIdx.x;
    const int tile0 = blockIdx.x * TM;

    if (tile0 >= g_total) {              // surplus block: stale g_order beyond
        if (t == 0) g_partial[blockIdx.x] = 0.f;
        return;
    }

    int sp = 0;
#pragma unroll
    for (int s = 1; s < NOS; s++) if (tile0 >= g_base[s]) sp = s;

    // ---- stage weights, transposed + swizzled ----
    for (int e = t; e < IN * H1; e += 256) {
        int k = e >> 5, c = e & 31;
        sW0T[c * 128 + (((k >> 2) + (c >> 2)) & 31) * 4 + (k & 3)] = W0[sp * IN * H1 + e];
    }
    for (int e = t; e < H1 * H2; e += 256) {
        int k = e >> 5, c = e & 31;
        sW1T[c * 32 + (((k >> 2) + (c >> 2)) & 7) * 4 + (k & 3)] = W1[sp * H1 * H2 + e];
    }
    if (t < H1) sb0[t] = b0[sp * H1 + t];
    if (t < H2) { sb1[t] = b1[sp * H2 + t]; sW2[t] = W2[sp * H2 + t]; }
    if (t == 0) sb2[0] = b2[sp];
    if (t < TM) sidx[t] = g_order[tile0 + t];
    __syncthreads();

    // ---- stage desc tile: coalesced float4 global -> swizzled smem ----
    {
        const int w = t >> 5, l = t & 31;
#pragma unroll
        for (int rr = 0; rr < TM / 8; rr++) {
            int row = rr * 8 + w;
            int idx = sidx[row];
            float4 v = make_float4(0.f, 0.f, 0.f, 0.f);
            if (idx >= 0) v = *(const float4*)(desc + (size_t)idx * IN + l * 4);
            *(float4*)&sdesc[row * 128 + ((l + 2 * (row >> 2)) & 31) * 4] = v;
        }
    }
    __syncthreads();

    const int jg   = t & 7;      // cols jg*4..+3
    const int ag   = t >> 3;     // atoms ag*4..+3
    const int dkey = 2 * ag;

    // -------- layer 0: [128x128] @ [128x32], k-packed f32x2 --------
    ull a[4][4];
#pragma unroll
    for (int r = 0; r < 4; r++)
#pragma unroll
        for (int c = 0; c < 4; c++) a[r][c] = 0ull;

    {
        const float* dB = sdesc + ag * 512;
        const float* wB = sW0T + jg * 512;
#pragma unroll 8
        for (int kg = 0; kg < 32; kg++) {
            int gd = ((kg + dkey) & 31) << 2;
            int gw = ((kg + jg) & 31) << 2;
            ulonglong2 d0 = *(const ulonglong2*)(dB + gd);
            ulonglong2 d1 = *(const ulonglong2*)(dB + 128 + gd);
            ulonglong2 d2 = *(const ulonglong2*)(dB + 256 + gd);
            ulonglong2 d3 = *(const ulonglong2*)(dB + 384 + gd);
            ulonglong2 w0 = *(const ulonglong2*)(wB + gw);
            ulonglong2 w1 = *(const ulonglong2*)(wB + 128 + gw);
            ulonglong2 w2 = *(const ulonglong2*)(wB + 256 + gw);
            ulonglong2 w3 = *(const ulonglong2*)(wB + 384 + gw);
            FFMA2(a[0][0], d0.x, w0.x); FFMA2(a[0][0], d0.y, w0.y);
            FFMA2(a[0][1], d0.x, w1.x); FFMA2(a[0][1], d0.y, w1.y);
            FFMA2(a[0][2], d0.x, w2.x); FFMA2(a[0][2], d0.y, w2.y);
            FFMA2(a[0][3], d0.x, w3.x); FFMA2(a[0][3], d0.y, w3.y);
            FFMA2(a[1][0], d1.x, w0.x); FFMA2(a[1][0], d1.y, w0.y);
            FFMA2(a[1][1], d1.x, w1.x); FFMA2(a[1][1], d1.y, w1.y);
            FFMA2(a[1][2], d1.x, w2.x); FFMA2(a[1][2], d1.y, w2.y);
            FFMA2(a[1][3], d1.x, w3.x); FFMA2(a[1][3], d1.y, w3.y);
            FFMA2(a[2][0], d2.x, w0.x); FFMA2(a[2][0], d2.y, w0.y);
            FFMA2(a[2][1], d2.x, w1.x); FFMA2(a[2][1], d2.y, w1.y);
            FFMA2(a[2][2], d2.x, w2.x); FFMA2(a[2][2], d2.y, w2.y);
            FFMA2(a[2][3], d2.x, w3.x); FFMA2(a[2][3], d2.y, w3.y);
            FFMA2(a[3][0], d3.x, w0.x); FFMA2(a[3][0], d3.y, w0.y);
            FFMA2(a[3][1], d3.x, w1.x); FFMA2(a[3][1], d3.y, w1.y);
            FFMA2(a[3][2], d3.x, w2.x); FFMA2(a[3][2], d3.y, w2.y);
            FFMA2(a[3][3], d3.x, w3.x); FFMA2(a[3][3], d3.y, w3.y);
        }
    }
#pragma unroll
    for (int r = 0; r < 4; r++) {
        float4 o;
        o.x = fast_tanh(pairsum(a[r][0]) + sb0[jg * 4 + 0]);
        o.y = fast_tanh(pairsum(a[r][1]) + sb0[jg * 4 + 1]);
        o.z = fast_tanh(pairsum(a[r][2]) + sb0[jg * 4 + 2]);
        o.w = fast_tanh(pairsum(a[r][3]) + sb0[jg * 4 + 3]);
        *(float4*)&sh1[(ag * 4 + r) * 32 + ((jg + dkey) & 7) * 4] = o;
    }
    __syncthreads();

    // -------- layer 1: [128x32] @ [32x32], k-packed f32x2 --------
#pragma unroll
    for (int r = 0; r < 4; r++)
#pragma unroll
        for (int c = 0; c < 4; c++) a[r][c] = 0ull;

    {
        const float* dB = sh1 + ag * 128;
        const float* wB = sW1T + jg * 128;
#pragma unroll
        for (int kg = 0; kg < 8; kg++) {
            int gd = ((kg + dkey) & 7) << 2;
            int gw = ((kg + jg) & 7) << 2;
            ulonglong2 d0 = *(const ulonglong2*)(dB + gd);
            ulonglong2 d1 = *(const ulonglong2*)(dB + 32 + gd);
            ulonglong2 d2 = *(const ulonglong2*)(dB + 64 + gd);
            ulonglong2 d3 = *(const ulonglong2*)(dB + 96 + gd);
            ulonglong2 w0 = *(const ulonglong2*)(wB + gw);
            ulonglong2 w1 = *(const ulonglong2*)(wB + 32 + gw);
            ulonglong2 w2 = *(const ulonglong2*)(wB + 64 + gw);
            ulonglong2 w3 = *(const ulonglong2*)(wB + 96 + gw);
            FFMA2(a[0][0], d0.x, w0.x); FFMA2(a[0][0], d0.y, w0.y);
            FFMA2(a[0][1], d0.x, w1.x); FFMA2(a[0][1], d0.y, w1.y);
            FFMA2(a[0][2], d0.x, w2.x); FFMA2(a[0][2], d0.y, w2.y);
            FFMA2(a[0][3], d0.x, w3.x); FFMA2(a[0][3], d0.y, w3.y);
            FFMA2(a[1][0], d1.x, w0.x); FFMA2(a[1][0], d1.y, w0.y);
            FFMA2(a[1][1], d1.x, w1.x); FFMA2(a[1][1], d1.y, w1.y);
            FFMA2(a[1][2], d1.x, w2.x); FFMA2(a[1][2], d1.y, w2.y);
            FFMA2(a[1][3], d1.x, w3.x); FFMA2(a[1][3], d1.y, w3.y);
            FFMA2(a[2][0], d2.x, w0.x); FFMA2(a[2][0], d2.y, w0.y);
            FFMA2(a[2][1], d2.x, w1.x); FFMA2(a[2][1], d2.y, w1.y);
            FFMA2(a[2][2], d2.x, w2.x); FFMA2(a[2][2], d2.y, w2.y);
            FFMA2(a[2][3], d2.x, w3.x); FFMA2(a[2][3], d2.y, w3.y);
            FFMA2(a[3][0], d3.x, w0.x); FFMA2(a[3][0], d3.y, w0.y);
            FFMA2(a[3][1], d3.x, w1.x); FFMA2(a[3][1], d3.y, w1.y);
            FFMA2(a[3][2], d3.x, w2.x); FFMA2(a[3][2], d3.y, w2.y);
            FFMA2(a[3][3], d3.x, w3.x); FFMA2(a[3][3], d3.y, w3.y);
        }
    }
#pragma unroll
    for (int r = 0; r < 4; r++) {
        float4 o;
        o.x = fast_tanh(pairsum(a[r][0]) + sb1[jg * 4 + 0]);
        o.y = fast_tanh(pairsum(a[r][1]) + sb1[jg * 4 + 1]);
        o.z = fast_tanh(pairsum(a[r][2]) + sb1[jg * 4 + 2]);
        o.w = fast_tanh(pairsum(a[r][3]) + sb1[jg * 4 + 3]);
        *(float4*)&sh2[(ag * 4 + r) * 32 + ((jg + dkey) & 7) * 4] = o;
    }
    __syncthreads();

    // -------- layer 2 + per-atom energy --------
    if (t < TM) {
        float e = 0.f;
        if (sidx[t] >= 0) {
            e = sb2[0];
            int key = 2 * (t >> 2);
#pragma unroll
            for (int k = 0; k < H2; k++)
                e += sh2[t * 32 + (((k >> 2) + key) & 7) * 4 + (k & 3)] * sW2[k];
        }
        sred[t] = e;
    }
    __syncthreads();

    if (t < 64) sred[t] += sred[t + 64];
    __syncthreads();
    if (t < 32) {
        float v = sred[t] + sred[t + 32];
#pragma unroll
        for (int o = 16; o > 0; o >>= 1) v += __shfl_down_sync(0xffffffffu, v, o);
        if (t == 0) g_partial[blockIdx.x] = v;
    }
}

// ---------------- deterministic final reduction ----------------
__global__ void k_reduce(float* out, int nb) {
    __shared__ float s[1024];
    const int t = threadIdx.x;
    float v = 0.f;
    for (int i = t; i < nb; i += 1024) v += g_partial[i];
    s[t] = v;
    __syncthreads();
#pragma unroll
    for (int o = 512; o > 32; o >>= 1) {
        if (t < o) s[t] += s[t + o];
        __syncthreads();
    }
    if (t < 32) {
        float x = s[t] + s[t + 32];
#pragma unroll
        for (int o = 16; o > 0; o >>= 1) x += __shfl_down_sync(0xffffffffu, x, o);
        if (t == 0) out[0] = x;
    }
}

// ---------------- launcher ----------------
extern "C" void kernel_launch(void* const* d_in, const int* in_sizes, int n_in,
                              void* d_out, int out_size)
{
    const float* desc    = (const float*)d_in[0];
    const void*  species = d_in[1];
    const float* W0 = (const float*)d_in[2];
    const float* b0 = (const float*)d_in[3];
    const float* W1 = (const float*)d_in[4];
    const float* b1 = (const float*)d_in[5];
    const float* W2 = (const float*)d_in[6];
    const float* b2 = (const float*)d_in[7];

    int n = in_sizes[1];
    if (n > MAXN) n = MAXN;

    int nb_atoms = (n + 255) / 256;
    int nb_mlp   = (n + TM - 1) / TM + NOS;
    if (nb_mlp > MAXNB) nb_mlp = MAXNB;

    cudaFuncSetAttribute(k_mlp, cudaFuncAttributeMaxDynamicSharedMemorySize, SMEM_BYTES);

    k_init<<<1, 256>>>((const unsigned long long*)species, n);
    k_count<<<nb_atoms, 256>>>(species, n);
    k_offsets<<<1, 1>>>();
    k_pad<<<1, NOS * TM>>>();
    k_scatter<<<nb_atoms, 256>>>(species, n);
    k_mlp<<<nb_mlp, 256, SMEM_BYTES>>>(desc, W0, b0, W1, b1, W2, b2);
    k_reduce<<<1, 1024>>>((float*)d_out, nb_mlp);
}

// round 4
// speedup vs baseline: 2.2299x; 2.0149x over previous
#include <cuda_runtime.h>
#include <cstdint>

#define MAXN   500000
#define IN     128
#define H1     32
#define H2     32
#define NOS    4
#define TM     128
#define MAXNB  3912
#define PADN   (MAXNB * TM)

// ---- smem byte offsets (k_mlp) ----
#define OFF_A     0          // A / h tile: [128 rows][132 floats]  = 67584 B
#define OFF_W0    67584      // W0: [k=128][40 floats]              = 20480 B
#define OFF_W1    88064      // W1: [k=32][40 floats]               = 5120 B
#define OFF_B0    93184
#define OFF_B1    93312
#define OFF_W2    93440
#define OFF_B2    93568
#define OFF_SIDX  93584      // 128 ints
#define OFF_SRED  94096      // 128 floats
#define SMEM_BYTES 94720

__device__ __forceinline__ uint32_t f2tf32(float x) {
    uint32_t r;
    asm("cvt.rna.tf32.f32 %0, %1;" : "=r"(r) : "f"(x));
    return r;
}
__device__ __forceinline__ float fast_tanh(float x) {
    float e, r;
    asm("ex2.approx.f32 %0, %1;" : "=f"(e) : "f"(x * 2.885390081777927f));
    asm("rcp.approx.f32 %0, %1;" : "=f"(r) : "f"(e + 1.0f));
    return fmaf(-2.0f, r, 1.0f);
}
__device__ __forceinline__ void mma8(float& d0, float& d1, float& d2, float& d3,
                                     uint32_t a0, uint32_t a1, uint32_t a2, uint32_t a3,
                                     uint32_t b0, uint32_t b1) {
    asm volatile(
        "mma.sync.aligned.m16n8k8.row.col.f32.tf32.tf32.f32 "
        "{%0,%1,%2,%3}, {%4,%5,%6,%7}, {%8,%9}, {%0,%1,%2,%3};"
        : "+f"(d0), "+f"(d1), "+f"(d2), "+f"(d3)
        : "r"(a0), "r"(a1), "r"(a2), "r"(a3), "r"(b0), "r"(b1));
}

// ---------------- device scratch ----------------
__device__ int   g_is64;
__device__ int   g_counts[NOS];
__device__ int   g_base[NOS];
__device__ int   g_cursor[NOS];
__device__ int   g_total;
__device__ int   g_order[PADN];
__device__ float g_partial[MAXNB];

__device__ __forceinline__ int ld_species(const void* sp, int i) {
    if (g_is64) return (int)((const long long*)sp)[i];
    return ((const int*)sp)[i];
}

// ---------------- prep kernels ----------------
__global__ void k_init(const unsigned long long* sp, int n) {
    __shared__ int bad;
    if (threadIdx.x == 0) bad = 0;
    if (threadIdx.x < NOS) g_counts[threadIdx.x] = 0;
    __syncthreads();
    int lim = (n / 2 < 2048) ? (n / 2) : 2048;
    for (int i = threadIdx.x; i < lim; i += 256)
        if (sp[i] >= 4ull) bad = 1;
    __syncthreads();
    if (threadIdx.x == 0) g_is64 = bad ? 0 : 1;
}

__global__ void k_count(const void* sp, int n) {
    __shared__ int h[NOS];
    if (threadIdx.x < NOS) h[threadIdx.x] = 0;
    __syncthreads();
    int i = blockIdx.x * blockDim.x + threadIdx.x;
    if (i < n) atomicAdd(&h[ld_species(sp, i)], 1);
    __syncthreads();
    if (threadIdx.x < NOS && h[threadIdx.x] > 0)
        atomicAdd(&g_counts[threadIdx.x], h[threadIdx.x]);
}

__global__ void k_offsets() {
    int base = 0;
#pragma unroll
    for (int s = 0; s < NOS; s++) {
        g_base[s]   = base;
        g_cursor[s] = base;
        base += ((g_counts[s] + TM - 1) / TM) * TM;
    }
    g_total = base;
}

__global__ void k_pad() {
    int t = threadIdx.x;
    int s = t / TM, j = t % TM;
    int cnt  = g_counts[s];
    int tile = ((cnt + TM - 1) / TM) * TM;
    int pos  = cnt + j;
    if (pos < tile) g_order[g_base[s] + pos] = -1;
}

__global__ void k_scatter(const void* sp, int n) {
    __shared__ int h[NOS];
    __shared__ int basebuf[NOS];
    if (threadIdx.x < NOS) h[threadIdx.x] = 0;
    __syncthreads();
    int i = blockIdx.x * blockDim.x + threadIdx.x;
    int s = 0, r = 0;
    bool valid = (i < n);
    if (valid) {
        s = ld_species(sp, i);
        r = atomicAdd(&h[s], 1);
    }
    __syncthreads();
    if (threadIdx.x < NOS && h[threadIdx.x] > 0)
        basebuf[threadIdx.x] = atomicAdd(&g_cursor[threadIdx.x], h[threadIdx.x]);
    __syncthreads();
    if (valid) g_order[basebuf[s] + r] = i;
}

// ---------------- HMMA tf32 fused MLP, one 128-atom tile per block ------
__global__ void __launch_bounds__(128, 2)
k_mlp(const float* __restrict__ desc,
      const float* __restrict__ W0, const float* __restrict__ b0,
      const float* __restrict__ W1, const float* __restrict__ b1,
      const float* __restrict__ W2, const float* __restrict__ b2)
{
    extern __shared__ char smc[];
    const int t = threadIdx.x, wid = t >> 5, lane = t & 31;
    const int gid = lane >> 2, tid = lane & 3;     // mma fragment coords
    const int tile0 = blockIdx.x * TM;

    if (tile0 >= g_total) {
        if (t == 0) g_partial[blockIdx.x] = 0.f;
        return;
    }

    int sp = 0;
#pragma unroll
    for (int s = 1; s < NOS; s++) if (tile0 >= g_base[s]) sp = s;

    uint32_t* sA  = (uint32_t*)(smc + OFF_A);      // [row][132]
    uint32_t* sW0 = (uint32_t*)(smc + OFF_W0);     // [k][40]
    uint32_t* sW1 = (uint32_t*)(smc + OFF_W1);     // [k][40]
    float*    vb0 = (float*)(smc + OFF_B0);
    float*    vb1 = (float*)(smc + OFF_B1);
    float*    vw2 = (float*)(smc + OFF_W2);
    float*    vb2 = (float*)(smc + OFF_B2);
    int*      sidx = (int*)(smc + OFF_SIDX);
    float*    sred = (float*)(smc + OFF_SRED);

    // ---- stage W0 [k=128][c=32] -> sW0[k*40+c] (tf32) ----
    {
        const float4* w4 = (const float4*)(W0 + sp * IN * H1);
#pragma unroll
        for (int e = t; e < IN * H1 / 4; e += 128) {
            int k = e >> 3, c = (e & 7) * 4;
            float4 v = w4[e];
            uint32_t* dst = sW0 + k * 40 + c;
            dst[0] = f2tf32(v.x); dst[1] = f2tf32(v.y);
            dst[2] = f2tf32(v.z); dst[3] = f2tf32(v.w);
        }
    }
    // ---- stage W1 [k=32][c=32] -> sW1[k*40+c] ----
    {
        const float4* w4 = (const float4*)(W1 + sp * H1 * H2);
#pragma unroll
        for (int e = t; e < H1 * H2 / 4; e += 128) {
            int k = e >> 3, c = (e & 7) * 4;
            float4 v = w4[e];
            uint32_t* dst = sW1 + k * 40 + c;
            dst[0] = f2tf32(v.x); dst[1] = f2tf32(v.y);
            dst[2] = f2tf32(v.z); dst[3] = f2tf32(v.w);
        }
    }
    if (t < H1) vb0[t] = b0[sp * H1 + t];
    if (t < H2) { vb1[t] = b1[sp * H2 + t]; vw2[t] = W2[sp * H2 + t]; }
    if (t == 0) vb2[0] = b2[sp];

    // ---- stage desc tile -> sA[row][132] (tf32) ----
    const int myidx = g_order[tile0 + t];
    if (t < TM) sidx[t] = myidx;
#pragma unroll 4
    for (int r = 0; r < 32; r++) {
        int row = wid * 32 + r;
        int idx = __shfl_sync(0xffffffffu, myidx, r);
        float4 v = make_float4(0.f, 0.f, 0.f, 0.f);
        if (idx >= 0) v = *(const float4*)(desc + (size_t)idx * IN + lane * 4);
        uint4 u;
        u.x = f2tf32(v.x); u.y = f2tf32(v.y); u.z = f2tf32(v.z); u.w = f2tf32(v.w);
        *(uint4*)(sA + row * 132 + lane * 4) = u;
    }
    __syncthreads();

    const int wbase = wid * 32;
    float d[2][4][4];
#pragma unroll
    for (int mt = 0; mt < 2; mt++)
#pragma unroll
        for (int nt = 0; nt < 4; nt++)
#pragma unroll
            for (int i = 0; i < 4; i++) d[mt][nt][i] = 0.f;

    // -------- layer 0: [128x128] @ [128x32], 16 k-steps --------
#pragma unroll
    for (int kk = 0; kk < 16; kk++) {
        const int k0 = kk * 8;
        uint32_t af[2][4];
#pragma unroll
        for (int mt = 0; mt < 2; mt++) {
            const uint32_t* ab = sA + (wbase + mt * 16 + gid) * 132 + k0 + tid;
            af[mt][0] = ab[0];
            af[mt][1] = ab[8 * 132];
            af[mt][2] = ab[4];
            af[mt][3] = ab[8 * 132 + 4];
        }
#pragma unroll
        for (int nt = 0; nt < 4; nt++) {
            const uint32_t* bb = sW0 + (k0 + tid) * 40 + nt * 8 + gid;
            uint32_t b0f = bb[0], b1f = bb[4 * 40];
            mma8(d[0][nt][0], d[0][nt][1], d[0][nt][2], d[0][nt][3],
                 af[0][0], af[0][1], af[0][2], af[0][3], b0f, b1f);
            mma8(d[1][nt][0], d[1][nt][1], d[1][nt][2], d[1][nt][3],
                 af[1][0], af[1][1], af[1][2], af[1][3], b0f, b1f);
        }
    }

    // -------- epilogue 0: bias + tanh -> tf32 -> sA (own rows only) -----
#pragma unroll
    for (int mt = 0; mt < 2; mt++) {
        int R0 = wbase + mt * 16 + gid;
#pragma unroll
        for (int nt = 0; nt < 4; nt++) {
            int c0 = nt * 8 + 2 * tid;
            sA[R0 * 132 + c0]            = f2tf32(fast_tanh(d[mt][nt][0] + vb0[c0]));
            sA[R0 * 132 + c0 + 1]        = f2tf32(fast_tanh(d[mt][nt][1] + vb0[c0 + 1]));
            sA[(R0 + 8) * 132 + c0]      = f2tf32(fast_tanh(d[mt][nt][2] + vb0[c0]));
            sA[(R0 + 8) * 132 + c0 + 1]  = f2tf32(fast_tanh(d[mt][nt][3] + vb0[c0 + 1]));
            d[mt][nt][0] = 0.f; d[mt][nt][1] = 0.f; d[mt][nt][2] = 0.f; d[mt][nt][3] = 0.f;
        }
    }
    __syncwarp();

    // -------- layer 1: [128x32] @ [32x32], 4 k-steps --------
#pragma unroll
    for (int kk = 0; kk < 4; kk++) {
        const int k0 = kk * 8;
        uint32_t af[2][4];
#pragma unroll
        for (int mt = 0; mt < 2; mt++) {
            const uint32_t* ab = sA + (wbase + mt * 16 + gid) * 132 + k0 + tid;
            af[mt][0] = ab[0];
            af[mt][1] = ab[8 * 132];
            af[mt][2] = ab[4];
            af[mt][3] = ab[8 * 132 + 4];
        }
#pragma unroll
        for (int nt = 0; nt < 4; nt++) {
            const uint32_t* bb = sW1 + (k0 + tid) * 40 + nt * 8 + gid;
            uint32_t b0f = bb[0], b1f = bb[4 * 40];
            mma8(d[0][nt][0], d[0][nt][1], d[0][nt][2], d[0][nt][3],
                 af[0][0], af[0][1], af[0][2], af[0][3], b0f, b1f);
            mma8(d[1][nt][0], d[1][nt][1], d[1][nt][2], d[1][nt][3],
                 af[1][0], af[1][1], af[1][2], af[1][3], b0f, b1f);
        }
    }

    // -------- epilogue 1: bias + tanh + W2 dot, 4-lane shuffle reduce ----
    {
        float p[4] = {0.f, 0.f, 0.f, 0.f};
#pragma unroll
        for (int mt = 0; mt < 2; mt++)
#pragma unroll
            for (int nt = 0; nt < 4; nt++) {
                int c0 = nt * 8 + 2 * tid;
                p[mt * 2 + 0] += fast_tanh(d[mt][nt][0] + vb1[c0])     * vw2[c0];
                p[mt * 2 + 0] += fast_tanh(d[mt][nt][1] + vb1[c0 + 1]) * vw2[c0 + 1];
                p[mt * 2 + 1] += fast_tanh(d[mt][nt][2] + vb1[c0])     * vw2[c0];
                p[mt * 2 + 1] += fast_tanh(d[mt][nt][3] + vb1[c0 + 1]) * vw2[c0 + 1];
            }
#pragma unroll
        for (int i = 0; i < 4; i++) {
            p[i] += __shfl_xor_sync(0xffffffffu, p[i], 1);
            p[i] += __shfl_xor_sync(0xffffffffu, p[i], 2);
        }
        if (tid == 0) {
            float bb2 = vb2[0];
#pragma unroll
            for (int mt = 0; mt < 2; mt++)
#pragma unroll
                for (int j = 0; j < 2; j++) {
                    int R = wbase + mt * 16 + j * 8 + gid;
                    sred[R] = (sidx[R] >= 0) ? (p[mt * 2 + j] + bb2) : 0.f;
                }
        }
    }
    __syncthreads();

    if (t < 64) sred[t] += sred[t + 64];
    __syncthreads();
    if (t < 32) {
        float v = sred[t] + sred[t + 32];
#pragma unroll
        for (int o = 16; o > 0; o >>= 1) v += __shfl_down_sync(0xffffffffu, v, o);
        if (t == 0) g_partial[blockIdx.x] = v;
    }
}

// ---------------- deterministic final reduction ----------------
__global__ void k_reduce(float* out, int nb) {
    __shared__ float s[1024];
    const int t = threadIdx.x;
    float v = 0.f;
    for (int i = t; i < nb; i += 1024) v += g_partial[i];
    s[t] = v;
    __syncthreads();
#pragma unroll
    for (int o = 512; o > 32; o >>= 1) {
        if (t < o) s[t] += s[t + o];
        __syncthreads();
    }
    if (t < 32) {
        float x = s[t] + s[t + 32];
#pragma unroll
        for (int o = 16; o > 0; o >>= 1) x += __shfl_down_sync(0xffffffffu, x, o);
        if (t == 0) out[0] = x;
    }
}

// ---------------- launcher ----------------
extern "C" void kernel_launch(void* const* d_in, const int* in_sizes, int n_in,
                              void* d_out, int out_size)
{
    const float* desc    = (const float*)d_in[0];
    const void*  species = d_in[1];
    const float* W0 = (const float*)d_in[2];
    const float* b0 = (const float*)d_in[3];
    const float* W1 = (const float*)d_in[4];
    const float* b1 = (const float*)d_in[5];
    const float* W2 = (const float*)d_in[6];
    const float* b2 = (const float*)d_in[7];

    int n = in_sizes[1];
    if (n > MAXN) n = MAXN;

    int nb_atoms = (n + 255) / 256;
    int nb_mlp   = (n + TM - 1) / TM + NOS;
    if (nb_mlp > MAXNB) nb_mlp = MAXNB;

    cudaFuncSetAttribute(k_mlp, cudaFuncAttributeMaxDynamicSharedMemorySize, SMEM_BYTES);

    k_init<<<1, 256>>>((const unsigned long long*)species, n);
    k_count<<<nb_atoms, 256>>>(species, n);
    k_offsets<<<1, 1>>>();
    k_pad<<<1, NOS * TM>>>();
    k_scatter<<<nb_atoms, 256>>>(species, n);
    k_mlp<<<nb_mlp, 128, SMEM_BYTES>>>(desc, W0, b0, W1, b1, W2, b2);
    k_reduce<<<1, 1024>>>((float*)d_out, nb_mlp);
}

// round 5
// speedup vs baseline: 3.1500x; 1.4126x over previous
#include <cuda_runtime.h>
#include <cuda_bf16.h>
#include <cstdint>

#define MAXN   500000
#define IN     128
#define H1     32
#define H2     32
#define NOS    4
#define TM     128
#define MAXNB  3912
#define PADN   (MAXNB * TM)
#define MAXCB  1954                  // ceil(MAXN/256)

typedef unsigned long long ull;

// ---- smem byte offsets (k_mlp) ----
#define OFF_A     0          // A tile  bf16 [128][136] = 34816
#define OFF_H     34816      // h tile  bf16 [128][40]  = 10240
#define OFF_W0    45056      // W0T     bf16 [32][136]  = 8704
#define OFF_W1    53760      // W1T     bf16 [32][40]   = 2560
#define OFF_B0    56320
#define OFF_B1    56448
#define OFF_W2    56576
#define OFF_B2    56704
#define OFF_SIDX  56720      // 128 ints
#define OFF_SRED  57232      // 128 floats
#define SMEM_BYTES 57856

__device__ __forceinline__ float fast_tanh(float x) {
    float e, r;
    asm("ex2.approx.f32 %0, %1;" : "=f"(e) : "f"(x * 2.885390081777927f));
    asm("rcp.approx.f32 %0, %1;" : "=f"(r) : "f"(e + 1.0f));
    return fmaf(-2.0f, r, 1.0f);
}
__device__ __forceinline__ uint32_t packbf2(float lo, float hi) {
    __nv_bfloat162 p = __floats2bfloat162_rn(lo, hi);
    return *(uint32_t*)&p;
}
__device__ __forceinline__ void mma16(float& d0, float& d1, float& d2, float& d3,
                                      uint32_t a0, uint32_t a1, uint32_t a2, uint32_t a3,
                                      uint32_t b0, uint32_t b1) {
    asm volatile(
        "mma.sync.aligned.m16n8k16.row.col.f32.bf16.bf16.f32 "
        "{%0,%1,%2,%3}, {%4,%5,%6,%7}, {%8,%9}, {%0,%1,%2,%3};"
        : "+f"(d0), "+f"(d1), "+f"(d2), "+f"(d3)
        : "r"(a0), "r"(a1), "r"(a2), "r"(a3), "r"(b0), "r"(b1));
}
__device__ __forceinline__ void ldm4(uint32_t& r0, uint32_t& r1, uint32_t& r2, uint32_t& r3,
                                     uint32_t addr) {
    asm volatile("ldmatrix.sync.aligned.m8n8.x4.shared.b16 {%0,%1,%2,%3}, [%4];"
                 : "=r"(r0), "=r"(r1), "=r"(r2), "=r"(r3) : "r"(addr));
}
__device__ __forceinline__ uint32_t smem_u32(const void* p) {
    uint32_t a;
    asm("{ .reg .u64 t; cvta.to.shared.u64 t, %1; cvt.u32.u64 %0, t; }" : "=r"(a) : "l"(p));
    return a;
}

// ---------------- device scratch ----------------
__device__ int   g_is64;
__device__ int   g_pcounts[MAXCB * NOS];
__device__ int   g_counts[NOS];
__device__ int   g_base[NOS];
__device__ int   g_cursor[NOS];
__device__ int   g_total;
__device__ int   g_order[PADN];
__device__ float g_partial[MAXNB];

// ---------------- count (self-detects int64 vs int32) ----------------
__global__ void k_count(const void* sp, int n) {
    __shared__ int h[NOS];
    __shared__ int bad;
    const int t = threadIdx.x;
    if (t < NOS) h[t] = 0;
    if (t == 0) bad = 0;
    __syncthreads();
    int lim = (n / 2 < 512) ? (n / 2) : 512;
    for (int i = t; i < lim; i += 256)
        if (((const ull*)sp)[i] >= 4ull) bad = 1;   // int32 data: hi word = next value
    __syncthreads();
    const int is64 = !bad;
    int i = blockIdx.x * 256 + t;
    if (i < n) {
        int s = is64 ? (int)((const long long*)sp)[i] : ((const int*)sp)[i];
        atomicAdd(&h[s], 1);
    }
    __syncthreads();
    if (t < NOS) g_pcounts[blockIdx.x * NOS + t] = h[t];
    if (t == 0 && blockIdx.x == 0) g_is64 = is64;
}

// ---------------- offsets: parallel partial-sum + bases ----------------
__global__ void k_offsets(int nb) {
    __shared__ int acc[128];
    const int t = threadIdx.x;
    const int s = t & 3, str = t >> 2;       // 32 strides per species
    int c = 0;
    for (int b = str; b < nb; b += 32) c += g_pcounts[b * NOS + s];
    acc[t] = c;
    __syncthreads();
    if (t < 8) {                              // sum 32 strides per species
        int tot = 0;
#pragma unroll
        for (int j = t & 3; j < 128; j += 4) tot += acc[j];
        if (t < 4) g_counts[t] = tot;
    }
    __syncthreads();
    if (t == 0) {
        int base = 0;
#pragma unroll
        for (int s2 = 0; s2 < NOS; s2++) {
            g_base[s2]   = base;
            g_cursor[s2] = base;
            base += ((g_counts[s2] + TM - 1) / TM) * TM;
        }
        g_total = base;
    }
}

// ---------------- scatter ----------------
__global__ void k_scatter(const void* sp, int n) {
    __shared__ int h[NOS];
    __shared__ int basebuf[NOS];
    const int t = threadIdx.x;
    if (t < NOS) h[t] = 0;
    __syncthreads();
    const int is64 = g_is64;
    int i = blockIdx.x * 256 + t;
    int s = 0, r = 0;
    bool valid = (i < n);
    if (valid) {
        s = is64 ? (int)((const long long*)sp)[i] : ((const int*)sp)[i];
        r = atomicAdd(&h[s], 1);
    }
    __syncthreads();
    if (t < NOS && h[t] > 0) basebuf[t] = atomicAdd(&g_cursor[t], h[t]);
    __syncthreads();
    if (valid) g_order[basebuf[s] + r] = i;
}

// ---------------- bf16 HMMA fused MLP, one 128-atom tile per block ------
__global__ void __launch_bounds__(128, 3)
k_mlp(const float* __restrict__ desc,
      const float* __restrict__ W0, const float* __restrict__ b0,
      const float* __restrict__ W1, const float* __restrict__ b1,
      const float* __restrict__ W2, const float* __restrict__ b2)
{
    extern __shared__ char smc[];
    const int t = threadIdx.x, wid = t >> 5, lane = t & 31;
    const int gid = lane >> 2, tid = lane & 3;
    const int tile0 = blockIdx.x * TM;

    if (tile0 >= g_total) {
        if (t == 0) g_partial[blockIdx.x] = 0.f;
        return;
    }

    int sp = 0;
#pragma unroll
    for (int s = 1; s < NOS; s++) if (tile0 >= g_base[s]) sp = s;
    const int cnt = g_counts[sp], segb = g_base[sp];

    __nv_bfloat16* sA  = (__nv_bfloat16*)(smc + OFF_A);    // [128][136]
    __nv_bfloat16* sH  = (__nv_bfloat16*)(smc + OFF_H);    // [128][40]
    __nv_bfloat16* sW0 = (__nv_bfloat16*)(smc + OFF_W0);   // [32][136] (n-major)
    __nv_bfloat16* sW1 = (__nv_bfloat16*)(smc + OFF_W1);   // [32][40]
    float* vb0 = (float*)(smc + OFF_B0);
    float* vb1 = (float*)(smc + OFF_B1);
    float* vw2 = (float*)(smc + OFF_W2);
    float* vb2 = (float*)(smc + OFF_B2);
    int*   sidx = (int*)(smc + OFF_SIDX);
    float* sred = (float*)(smc + OFF_SRED);

    // ---- stage W0 [k=128][c=32] -> sW0T[c][k] bf16 ----
    {
        const float4* w4 = (const float4*)(W0 + sp * IN * H1);
#pragma unroll
        for (int e = t; e < IN * H1 / 4; e += 128) {
            int k = e >> 3, c = (e & 7) * 4;
            float4 v = w4[e];
            sW0[(c + 0) * 136 + k] = __float2bfloat16_rn(v.x);
            sW0[(c + 1) * 136 + k] = __float2bfloat16_rn(v.y);
            sW0[(c + 2) * 136 + k] = __float2bfloat16_rn(v.z);
            sW0[(c + 3) * 136 + k] = __float2bfloat16_rn(v.w);
        }
    }
    // ---- stage W1 [k=32][c=32] -> sW1T[c][k] bf16 ----
    {
        const float4* w4 = (const float4*)(W1 + sp * H1 * H2);
#pragma unroll
        for (int e = t; e < H1 * H2 / 4; e += 128) {
            int k = e >> 3, c = (e & 7) * 4;
            float4 v = w4[e];
            sW1[(c + 0) * 40 + k] = __float2bfloat16_rn(v.x);
            sW1[(c + 1) * 40 + k] = __float2bfloat16_rn(v.y);
            sW1[(c + 2) * 40 + k] = __float2bfloat16_rn(v.z);
            sW1[(c + 3) * 40 + k] = __float2bfloat16_rn(v.w);
        }
    }
    if (t < H1) vb0[t] = b0[sp * H1 + t];
    if (t < H2) { vb1[t] = b1[sp * H2 + t]; vw2[t] = W2[sp * H2 + t]; }
    if (t == 0) vb2[0] = b2[sp];

    // ---- stage desc tile -> sA bf16 ----
    const int local = tile0 + t - segb;
    const int myidx = (local < cnt) ? g_order[tile0 + t] : -1;
    sidx[t] = myidx;
#pragma unroll 4
    for (int r = 0; r < 32; r++) {
        int row = wid * 32 + r;
        int idx = __shfl_sync(0xffffffffu, myidx, r);
        float4 v = make_float4(0.f, 0.f, 0.f, 0.f);
        if (idx >= 0) v = *(const float4*)(desc + (size_t)idx * IN + lane * 4);
        uint2 u;
        u.x = packbf2(v.x, v.y);
        u.y = packbf2(v.z, v.w);
        *(uint2*)(sA + row * 136 + lane * 4) = u;
    }
    __syncthreads();

    const int wbase = wid * 32;
    const uint32_t aAddr = smem_u32(sA);
    const uint32_t hAddr = smem_u32(sH);
    // ldmatrix lane geometry: row add = (q&1)*8 + lane%8, col add = (q>>1)*8 elems
    const int lrow = ((lane >> 3) & 1) * 8 + (lane & 7);
    const int lcol = (lane >> 4) * 8;

    float d[2][4][4];
#pragma unroll
    for (int mt = 0; mt < 2; mt++)
#pragma unroll
        for (int nt = 0; nt < 4; nt++)
#pragma unroll
            for (int i = 0; i < 4; i++) d[mt][nt][i] = 0.f;

    // -------- layer 0: [128x128] @ [128x32] bf16, 8 k16-steps --------
#pragma unroll
    for (int kk = 0; kk < 8; kk++) {
        const int k0 = kk * 16;
        uint32_t af[2][4];
#pragma unroll
        for (int mt = 0; mt < 2; mt++)
            ldm4(af[mt][0], af[mt][1], af[mt][2], af[mt][3],
                 aAddr + ((wbase + mt * 16 + lrow) * 136 + k0 + lcol) * 2);
#pragma unroll
        for (int nt = 0; nt < 4; nt++) {
            const __nv_bfloat16* bb = sW0 + (nt * 8 + gid) * 136 + k0 + 2 * tid;
            uint32_t b0f = *(const uint32_t*)bb;
            uint32_t b1f = *(const uint32_t*)(bb + 8);
            mma16(d[0][nt][0], d[0][nt][1], d[0][nt][2], d[0][nt][3],
                  af[0][0], af[0][1], af[0][2], af[0][3], b0f, b1f);
            mma16(d[1][nt][0], d[1][nt][1], d[1][nt][2], d[1][nt][3],
                  af[1][0], af[1][1], af[1][2], af[1][3], b0f, b1f);
        }
    }

    // -------- epilogue 0: bias + tanh -> bf16 -> sH (warp-local rows) ----
#pragma unroll
    for (int mt = 0; mt < 2; mt++) {
        int R0 = wbase + mt * 16 + gid;
#pragma unroll
        for (int nt = 0; nt < 4; nt++) {
            int c0 = nt * 8 + 2 * tid;
            *(uint32_t*)(sH + R0 * 40 + c0) =
                packbf2(fast_tanh(d[mt][nt][0] + vb0[c0]),
                        fast_tanh(d[mt][nt][1] + vb0[c0 + 1]));
            *(uint32_t*)(sH + (R0 + 8) * 40 + c0) =
                packbf2(fast_tanh(d[mt][nt][2] + vb0[c0]),
                        fast_tanh(d[mt][nt][3] + vb0[c0 + 1]));
            d[mt][nt][0] = 0.f; d[mt][nt][1] = 0.f;
            d[mt][nt][2] = 0.f; d[mt][nt][3] = 0.f;
        }
    }
    __syncwarp();

    // -------- layer 1: [128x32] @ [32x32] bf16, 2 k16-steps --------
#pragma unroll
    for (int kk = 0; kk < 2; kk++) {
        const int k0 = kk * 16;
        uint32_t af[2][4];
#pragma unroll
        for (int mt = 0; mt < 2; mt++)
            ldm4(af[mt][0], af[mt][1], af[mt][2], af[mt][3],
                 hAddr + ((wbase + mt * 16 + lrow) * 40 + k0 + lcol) * 2);
#pragma unroll
        for (int nt = 0; nt < 4; nt++) {
            const __nv_bfloat16* bb = sW1 + (nt * 8 + gid) * 40 + k0 + 2 * tid;
            uint32_t b0f = *(const uint32_t*)bb;
            uint32_t b1f = *(const uint32_t*)(bb + 8);
            mma16(d[0][nt][0], d[0][nt][1], d[0][nt][2], d[0][nt][3],
                  af[0][0], af[0][1], af[0][2], af[0][3], b0f, b1f);
            mma16(d[1][nt][0], d[1][nt][1], d[1][nt][2], d[1][nt][3],
                  af[1][0], af[1][1], af[1][2], af[1][3], b0f, b1f);
        }
    }

    // -------- epilogue 1: bias + tanh + W2 dot, 4-lane shuffle reduce ----
    {
        float p[4] = {0.f, 0.f, 0.f, 0.f};
#pragma unroll
        for (int mt = 0; mt < 2; mt++)
#pragma unroll
            for (int nt = 0; nt < 4; nt++) {
                int c0 = nt * 8 + 2 * tid;
                p[mt * 2 + 0] += fast_tanh(d[mt][nt][0] + vb1[c0])     * vw2[c0];
                p[mt * 2 + 0] += fast_tanh(d[mt][nt][1] + vb1[c0 + 1]) * vw2[c0 + 1];
                p[mt * 2 + 1] += fast_tanh(d[mt][nt][2] + vb1[c0])     * vw2[c0];
                p[mt * 2 + 1] += fast_tanh(d[mt][nt][3] + vb1[c0 + 1]) * vw2[c0 + 1];
            }
#pragma unroll
        for (int i = 0; i < 4; i++) {
            p[i] += __shfl_xor_sync(0xffffffffu, p[i], 1);
            p[i] += __shfl_xor_sync(0xffffffffu, p[i], 2);
        }
        if (tid == 0) {
            float bb2 = vb2[0];
#pragma unroll
            for (int mt = 0; mt < 2; mt++)
#pragma unroll
                for (int j = 0; j < 2; j++) {
                    int R = wbase + mt * 16 + j * 8 + gid;
                    sred[R] = (sidx[R] >= 0) ? (p[mt * 2 + j] + bb2) : 0.f;
                }
        }
    }
    __syncthreads();

    if (t < 64) sred[t] += sred[t + 64];
    __syncthreads();
    if (t < 32) {
        float v = sred[t] + sred[t + 32];
#pragma unroll
        for (int o = 16; o > 0; o >>= 1) v += __shfl_down_sync(0xffffffffu, v, o);
        if (t == 0) g_partial[blockIdx.x] = v;
    }
}

// ---------------- deterministic final reduction ----------------
__global__ void k_reduce(float* out, int nb) {
    __shared__ float s[1024];
    const int t = threadIdx.x;
    float v = 0.f;
    for (int i = t; i < nb; i += 1024) v += g_partial[i];
    s[t] = v;
    __syncthreads();
#pragma unroll
    for (int o = 512; o > 32; o >>= 1) {
        if (t < o) s[t] += s[t + o];
        __syncthreads();
    }
    if (t < 32) {
        float x = s[t] + s[t + 32];
#pragma unroll
        for (int o = 16; o > 0; o >>= 1) x += __shfl_down_sync(0xffffffffu, x, o);
        if (t == 0) out[0] = x;
    }
}

// ---------------- launcher ----------------
extern "C" void kernel_launch(void* const* d_in, const int* in_sizes, int n_in,
                              void* d_out, int out_size)
{
    const float* desc    = (const float*)d_in[0];
    const void*  species = d_in[1];
    const float* W0 = (const float*)d_in[2];
    const float* b0 = (const float*)d_in[3];
    const float* W1 = (const float*)d_in[4];
    const float* b1 = (const float*)d_in[5];
    const float* W2 = (const float*)d_in[6];
    const float* b2 = (const float*)d_in[7];

    int n = in_sizes[1];
    if (n > MAXN) n = MAXN;

    int nb_atoms = (n + 255) / 256;
    if (nb_atoms > MAXCB) nb_atoms = MAXCB;
    int nb_mlp = (n + TM - 1) / TM + NOS;
    if (nb_mlp > MAXNB) nb_mlp = MAXNB;

    cudaFuncSetAttribute(k_mlp, cudaFuncAttributeMaxDynamicSharedMemorySize, SMEM_BYTES);

    k_count<<<nb_atoms, 256>>>(species, n);
    k_offsets<<<1, 128>>>(nb_atoms);
    k_scatter<<<nb_atoms, 256>>>(species, n);
    k_mlp<<<nb_mlp, 128, SMEM_BYTES>>>(desc, W0, b0, W1, b1, W2, b2);
    k_reduce<<<1, 1024>>>((float*)d_out, nb_mlp);
}